// round 9
// baseline (speedup 1.0000x reference)
#include <cuda_runtime.h>
#include <cuda_fp16.h>

#define BATCH   64
#define NATOMS  64
#define HDIM    256
#define NROWS   (2 * BATCH * NATOMS)   /* 8192 */
#define H2      (HDIM / 2)             /* 128 half2 per row */

/* s = [h1@W1[:H]+b1 ; h2@W1[H:]] packed half2 (4 MB) */
__device__ unsigned g_sh[NROWS * H2];
__device__ float g_rp[BATCH * NATOMS * 2];   /* row partials, 2 j-halves */
__device__ float g_cp[BATCH * NATOMS * 2];   /* col partials, 2 i-halves */

__device__ __forceinline__ unsigned pack_h2(float x, float y) {
    __half2 h = __floats2half2_rn(x, y);
    return *reinterpret_cast<unsigned*>(&h);
}
__device__ __forceinline__ unsigned tanh2u(unsigned x) {
    unsigned y; asm("tanh.approx.f16x2 %0, %1;" : "=r"(y) : "r"(x)); return y;
}
__device__ __forceinline__ __half2 u2h(unsigned u) {
    return *reinterpret_cast<__half2*>(&u);
}
__device__ __forceinline__ unsigned hadd2u(unsigned a, unsigned b) {
    __half2 r = __hadd2(u2h(a), u2h(b));
    return *reinterpret_cast<unsigned*>(&r);
}
__device__ __forceinline__ void cp_async16(void* smem, const void* gmem) {
    unsigned s = (unsigned)__cvta_generic_to_shared(smem);
    asm volatile("cp.async.cg.shared.global [%0], [%1], 16;" :: "r"(s), "l"(gmem));
}

/* ===== tf32 tensor GEMM (R6-proven body), per-half grid (64,4) ===== */
__global__ void __launch_bounds__(128) gemm_kernel(
    const float* __restrict__ h1, const float* __restrict__ h2,
    const float* __restrict__ W1, const float* __restrict__ b1, int half)
{
    __shared__ float As[2][64 * 36];
    __shared__ float Bs[2][32 * 72];

    const int bx = blockIdx.x;
    const bool second = (bx >= 32);
    const int row_local = half * 2048 + (bx & 31) * 64;   /* row in h1/h2 */
    const int row0 = (second ? BATCH * NATOMS : 0) + row_local;  /* row in g_sh */
    const int n0   = blockIdx.y * 64;
    const float* A = (second ? h2 : h1) + row_local * HDIM;
    const float* W = W1 + (second ? HDIM * HDIM : 0);

    const int tid = threadIdx.x;
    const int lane = tid & 31, w = tid >> 5;
    const int wm = w >> 1, wn = w & 1;
    const int gid = lane >> 2, tig = lane & 3;

    int ar[4], ac[4], bk[4], bn[4];
#pragma unroll
    for (int l = 0; l < 4; l++) {
        int f = tid + l * 128;
        ar[l] = f >> 3;  ac[l] = f & 7;
        bk[l] = f >> 4;  bn[l] = f & 15;
    }

    float acc[2][4][4];
#pragma unroll
    for (int mt = 0; mt < 2; mt++)
#pragma unroll
        for (int nt = 0; nt < 4; nt++)
#pragma unroll
            for (int q = 0; q < 4; q++) acc[mt][nt][q] = 0.f;

#pragma unroll
    for (int l = 0; l < 4; l++)
        cp_async16(&As[0][ar[l] * 36 + ac[l] * 4], A + ar[l] * HDIM + ac[l] * 4);
#pragma unroll
    for (int l = 0; l < 4; l++)
        cp_async16(&Bs[0][bk[l] * 72 + bn[l] * 4], W + bk[l] * HDIM + n0 + bn[l] * 4);
    asm volatile("cp.async.commit_group;");

    for (int kci = 0; kci < 8; kci++) {
        const int s = kci & 1;
        if (kci + 1 < 8) {
            const int kc = (kci + 1) * 32;
#pragma unroll
            for (int l = 0; l < 4; l++)
                cp_async16(&As[s ^ 1][ar[l] * 36 + ac[l] * 4],
                           A + ar[l] * HDIM + kc + ac[l] * 4);
#pragma unroll
            for (int l = 0; l < 4; l++)
                cp_async16(&Bs[s ^ 1][bk[l] * 72 + bn[l] * 4],
                           W + (kc + bk[l]) * HDIM + n0 + bn[l] * 4);
            asm volatile("cp.async.commit_group;");
            asm volatile("cp.async.wait_group 1;");
        } else {
            asm volatile("cp.async.wait_group 0;");
        }
        __syncthreads();

        const unsigned* Au = (const unsigned*)As[s];
        const unsigned* Bu = (const unsigned*)Bs[s];
#pragma unroll
        for (int ks = 0; ks < 4; ks++) {
            unsigned a[2][4], bfr[4][2];
#pragma unroll
            for (int mt = 0; mt < 2; mt++) {
                int r = wm * 32 + mt * 16 + gid;
                int kk = ks * 8 + tig;
                a[mt][0] = Au[r * 36 + kk];
                a[mt][1] = Au[(r + 8) * 36 + kk];
                a[mt][2] = Au[r * 36 + kk + 4];
                a[mt][3] = Au[(r + 8) * 36 + kk + 4];
            }
#pragma unroll
            for (int nt = 0; nt < 4; nt++) {
                int c = wn * 32 + nt * 8 + gid;
                bfr[nt][0] = Bu[(ks * 8 + tig) * 72 + c];
                bfr[nt][1] = Bu[(ks * 8 + tig + 4) * 72 + c];
            }
#pragma unroll
            for (int mt = 0; mt < 2; mt++)
#pragma unroll
                for (int nt = 0; nt < 4; nt++)
                    asm volatile(
                        "mma.sync.aligned.m16n8k8.row.col.f32.tf32.tf32.f32 "
                        "{%0,%1,%2,%3}, {%4,%5,%6,%7}, {%8,%9}, {%0,%1,%2,%3};"
                        : "+f"(acc[mt][nt][0]), "+f"(acc[mt][nt][1]),
                          "+f"(acc[mt][nt][2]), "+f"(acc[mt][nt][3])
                        : "r"(a[mt][0]), "r"(a[mt][1]), "r"(a[mt][2]), "r"(a[mt][3]),
                          "r"(bfr[nt][0]), "r"(bfr[nt][1]));
        }
        __syncthreads();
    }

#pragma unroll
    for (int mt = 0; mt < 2; mt++) {
        int r = row0 + wm * 32 + mt * 16 + gid;
#pragma unroll
        for (int nt = 0; nt < 4; nt++) {
            int col = n0 + wn * 32 + nt * 8 + tig * 2;
            float bx_ = 0.f, by_ = 0.f;
            if (!second) { float2 bv = *(const float2*)(b1 + col); bx_ = bv.x; by_ = bv.y; }
            g_sh[r * H2 + (col >> 1)]       = pack_h2(acc[mt][nt][0] + bx_, acc[mt][nt][1] + by_);
            g_sh[(r + 8) * H2 + (col >> 1)] = pack_h2(acc[mt][nt][2] + bx_, acc[mt][nt][3] + by_);
        }
    }
}

/* ===== score: R2-proven body, graph offset b0, grid (2,2,32) ===== */
__global__ void __launch_bounds__(256) score_kernel(const float* __restrict__ W2, int b0)
{
    __shared__ unsigned s1s[32 * 128];
    __shared__ unsigned s2s[32 * 129];
    __shared__ float2   w2s[128];
    __shared__ float    colbuf[8][32];

    const int jh = blockIdx.x, ih = blockIdx.y, b = b0 + blockIdx.z;
    const int tid = threadIdx.x, lane = tid & 31, w = tid >> 5;

    if (tid < 128) w2s[tid] = *(const float2*)(W2 + tid * 2);

    const unsigned* s1g = g_sh + (b * NATOMS + ih * 32) * H2;
#pragma unroll
    for (int l = 0; l < 4; l++) {
        int f = tid + l * 256;
        *(uint4*)&s1s[f * 4] = *(const uint4*)(s1g + f * 4);
    }
    const unsigned* s2g = g_sh + (BATCH * NATOMS + b * NATOMS + jh * 32) * H2;
#pragma unroll
    for (int l = 0; l < 4; l++) {
        int f = tid + l * 256;
        int j = f >> 5, q = f & 31;
        uint4 v = *(const uint4*)(s2g + f * 4);
        unsigned* d = &s2s[j * 129 + q * 4];
        d[0] = v.x; d[1] = v.y; d[2] = v.z; d[3] = v.w;
    }
    __syncthreads();

    const unsigned* s2row = &s2s[lane * 129];
    float accA[4], accB[4];
#pragma unroll
    for (int ii = 0; ii < 4; ii++) { accA[ii] = 0.f; accB[ii] = 0.f; }

#pragma unroll 4
    for (int hh = 0; hh < 128; hh++) {
        float2 wv = w2s[hh];
        unsigned b2 = s2row[hh];
#pragma unroll
        for (int ii = 0; ii < 4; ii++) {
            unsigned a2 = s1s[(w * 4 + ii) * 128 + hh];
            unsigned th = tanh2u(hadd2u(a2, b2));
            float2 tf = __half22float2(u2h(th));
            accA[ii] = fmaf(wv.x, tf.x, accA[ii]);
            accB[ii] = fmaf(wv.y, tf.y, accB[ii]);
        }
    }

    float colacc = 0.f;
#pragma unroll
    for (int ii = 0; ii < 4; ii++) {
        float e = __expf(accA[ii] + accB[ii]);
        colacc += e;
        float rs = e;
#pragma unroll
        for (int o = 16; o > 0; o >>= 1)
            rs += __shfl_xor_sync(0xffffffffu, rs, o);
        if (lane == 0)
            g_rp[(b * NATOMS + ih * 32 + w * 4 + ii) * 2 + jh] = rs;
    }
    colbuf[w][lane] = colacc;
    __syncthreads();
    if (tid < 32) {
        float s = 0.f;
#pragma unroll
        for (int ww = 0; ww < 8; ww++) s += colbuf[ww][tid];
        g_cp[(b * NATOMS + jh * 32 + tid) * 2 + ih] = s;
    }
}

/* ---------------- normalize ---------------- */
__global__ void __launch_bounds__(64) finalize_kernel(float* __restrict__ out)
{
    int b = blockIdx.x, i = threadIdx.x;
    float r = g_rp[(b * 64 + i) * 2] + g_rp[(b * 64 + i) * 2 + 1];
    float c = g_cp[(b * 64 + i) * 2] + g_cp[(b * 64 + i) * 2 + 1];
    __shared__ float red[64];
    red[i] = r;
    __syncthreads();
    if (i < 32) {
        float v = red[i] + red[i + 32];
#pragma unroll
        for (int o = 16; o > 0; o >>= 1)
            v += __shfl_xor_sync(0xffffffffu, v, o);
        if (i == 0) red[0] = v;
    }
    __syncthreads();
    float inv = 1.f / red[0];
    out[b * 64 + i] = r * inv;
    out[BATCH * NATOMS + b * 64 + i] = c * inv;
}

/* side stream + events, created once at load (handles only, no device mem) */
static cudaStream_t g_st2 = nullptr;
static cudaEvent_t  g_evf = nullptr, g_evj = nullptr;
namespace {
struct HxStreamInit {
    HxStreamInit() {
        if (cudaStreamCreateWithFlags(&g_st2, cudaStreamNonBlocking) != cudaSuccess) {
            g_st2 = nullptr; return;
        }
        if (cudaEventCreateWithFlags(&g_evf, cudaEventDisableTiming) != cudaSuccess ||
            cudaEventCreateWithFlags(&g_evj, cudaEventDisableTiming) != cudaSuccess) {
            g_st2 = nullptr;
        }
    }
} g_hx_stream_init;
}

extern "C" void kernel_launch(void* const* d_in, const int* in_sizes, int n_in,
                              void* d_out, int out_size)
{
    const float *h1 = nullptr, *h2 = nullptr, *W1 = nullptr,
                *b1 = nullptr, *W2 = nullptr;
    for (int idx = 0; idx < n_in; idx++) {
        int sz = in_sizes[idx];
        if (sz == BATCH * NATOMS * HDIM) {
            if (!h1) h1 = (const float*)d_in[idx];
            else if (!h2) h2 = (const float*)d_in[idx];
        } else if (sz == 2 * HDIM * HDIM) {
            W1 = (const float*)d_in[idx];
        } else if (sz == HDIM) {
            if (!b1) b1 = (const float*)d_in[idx];
            else if (!W2) W2 = (const float*)d_in[idx];
        }
    }
    float* out = (float*)d_out;

    if (g_st2) {
        /* pipelined: G1 -> (S1 || G2) -> S2 -> finalize */
        gemm_kernel<<<dim3(64, 4), 128>>>(h1, h2, W1, b1, 0);
        cudaEventRecord(g_evf, 0);
        cudaStreamWaitEvent(g_st2, g_evf, 0);
        gemm_kernel<<<dim3(64, 4), 128, 0, g_st2>>>(h1, h2, W1, b1, 1);
        score_kernel<<<dim3(2, 2, 32), 256>>>(W2, 0);
        score_kernel<<<dim3(2, 2, 32), 256, 0, g_st2>>>(W2, 32);
        cudaEventRecord(g_evj, g_st2);
        cudaStreamWaitEvent(0, g_evj, 0);
        finalize_kernel<<<BATCH, 64>>>(out);
    } else {
        /* sequential fallback: identical work */
        gemm_kernel<<<dim3(64, 4), 128>>>(h1, h2, W1, b1, 0);
        gemm_kernel<<<dim3(64, 4), 128>>>(h1, h2, W1, b1, 1);
        score_kernel<<<dim3(2, 2, 32), 256>>>(W2, 0);
        score_kernel<<<dim3(2, 2, 32), 256>>>(W2, 32);
        finalize_kernel<<<BATCH, 64>>>(out);
    }
}

// round 10
// speedup vs baseline: 1.1251x; 1.1251x over previous
#include <cuda_runtime.h>
#include <cuda_fp16.h>

#define BATCH   64
#define NATOMS  64
#define HDIM    256
#define NROWS   (2 * BATCH * NATOMS)   /* 8192 */
#define H2      (HDIM / 2)             /* 128 half2 per row */

/* s = [h1@W1[:H]+b1 ; h2@W1[H:]] packed half2 (4 MB) */
__device__ unsigned g_sh[NROWS * H2];
__device__ float g_rp[BATCH * NATOMS * 2];   /* row partials, 2 j-halves */
__device__ float g_c[BATCH * NATOMS];        /* col sums (complete)      */

__device__ __forceinline__ unsigned pack_h2(float x, float y) {
    __half2 h = __floats2half2_rn(x, y);
    return *reinterpret_cast<unsigned*>(&h);
}
__device__ __forceinline__ unsigned tanh2u(unsigned x) {
    unsigned y; asm("tanh.approx.f16x2 %0, %1;" : "=r"(y) : "r"(x)); return y;
}
__device__ __forceinline__ __half2 u2h(unsigned u) {
    return *reinterpret_cast<__half2*>(&u);
}
__device__ __forceinline__ unsigned hadd2u(unsigned a, unsigned b) {
    __half2 r = __hadd2(u2h(a), u2h(b));
    return *reinterpret_cast<unsigned*>(&r);
}
__device__ __forceinline__ void cp_async16(void* smem, const void* gmem) {
    unsigned s = (unsigned)__cvta_generic_to_shared(smem);
    asm volatile("cp.async.cg.shared.global [%0], [%1], 16;" :: "r"(s), "l"(gmem));
}

/* ===== tf32 tensor GEMM: R3/R6-proven (64x64, 128 thr, 2-stage) ===== */
__global__ void __launch_bounds__(128) gemm_kernel(
    const float* __restrict__ h1, const float* __restrict__ h2,
    const float* __restrict__ W1, const float* __restrict__ b1)
{
    __shared__ float As[2][64 * 36];   /* [row][k], pad 36 -> conflict-free */
    __shared__ float Bs[2][32 * 72];   /* [k][n],   pad 72 -> conflict-free */

    const int row0 = blockIdx.x * 64;
    const int n0   = blockIdx.y * 64;
    const bool second = (row0 >= BATCH * NATOMS);
    const float* A = second ? h2 + (row0 - BATCH * NATOMS) * HDIM
                            : h1 + row0 * HDIM;
    const float* W = W1 + (second ? HDIM * HDIM : 0);

    const int tid = threadIdx.x;
    const int lane = tid & 31, w = tid >> 5;
    const int wm = w >> 1, wn = w & 1;
    const int gid = lane >> 2, tig = lane & 3;

    int ar[4], ac[4], bk[4], bn[4];
#pragma unroll
    for (int l = 0; l < 4; l++) {
        int f = tid + l * 128;
        ar[l] = f >> 3;  ac[l] = f & 7;
        bk[l] = f >> 4;  bn[l] = f & 15;
    }

    float acc[2][4][4];
#pragma unroll
    for (int mt = 0; mt < 2; mt++)
#pragma unroll
        for (int nt = 0; nt < 4; nt++)
#pragma unroll
            for (int q = 0; q < 4; q++) acc[mt][nt][q] = 0.f;

#pragma unroll
    for (int l = 0; l < 4; l++)
        cp_async16(&As[0][ar[l] * 36 + ac[l] * 4], A + ar[l] * HDIM + ac[l] * 4);
#pragma unroll
    for (int l = 0; l < 4; l++)
        cp_async16(&Bs[0][bk[l] * 72 + bn[l] * 4], W + bk[l] * HDIM + n0 + bn[l] * 4);
    asm volatile("cp.async.commit_group;");

    for (int kci = 0; kci < 8; kci++) {
        const int s = kci & 1;
        if (kci + 1 < 8) {
            const int kc = (kci + 1) * 32;
#pragma unroll
            for (int l = 0; l < 4; l++)
                cp_async16(&As[s ^ 1][ar[l] * 36 + ac[l] * 4],
                           A + ar[l] * HDIM + kc + ac[l] * 4);
#pragma unroll
            for (int l = 0; l < 4; l++)
                cp_async16(&Bs[s ^ 1][bk[l] * 72 + bn[l] * 4],
                           W + (kc + bk[l]) * HDIM + n0 + bn[l] * 4);
            asm volatile("cp.async.commit_group;");
            asm volatile("cp.async.wait_group 1;");
        } else {
            asm volatile("cp.async.wait_group 0;");
        }
        __syncthreads();

        const unsigned* Au = (const unsigned*)As[s];
        const unsigned* Bu = (const unsigned*)Bs[s];
#pragma unroll
        for (int ks = 0; ks < 4; ks++) {
            unsigned a[2][4], bfr[4][2];
#pragma unroll
            for (int mt = 0; mt < 2; mt++) {
                int r = wm * 32 + mt * 16 + gid;
                int kk = ks * 8 + tig;
                a[mt][0] = Au[r * 36 + kk];
                a[mt][1] = Au[(r + 8) * 36 + kk];
                a[mt][2] = Au[r * 36 + kk + 4];
                a[mt][3] = Au[(r + 8) * 36 + kk + 4];
            }
#pragma unroll
            for (int nt = 0; nt < 4; nt++) {
                int c = wn * 32 + nt * 8 + gid;
                bfr[nt][0] = Bu[(ks * 8 + tig) * 72 + c];
                bfr[nt][1] = Bu[(ks * 8 + tig + 4) * 72 + c];
            }
#pragma unroll
            for (int mt = 0; mt < 2; mt++)
#pragma unroll
                for (int nt = 0; nt < 4; nt++)
                    asm volatile(
                        "mma.sync.aligned.m16n8k8.row.col.f32.tf32.tf32.f32 "
                        "{%0,%1,%2,%3}, {%4,%5,%6,%7}, {%8,%9}, {%0,%1,%2,%3};"
                        : "+f"(acc[mt][nt][0]), "+f"(acc[mt][nt][1]),
                          "+f"(acc[mt][nt][2]), "+f"(acc[mt][nt][3])
                        : "r"(a[mt][0]), "r"(a[mt][1]), "r"(a[mt][2]), "r"(a[mt][3]),
                          "r"(bfr[nt][0]), "r"(bfr[nt][1]));
        }
        __syncthreads();
    }

#pragma unroll
    for (int mt = 0; mt < 2; mt++) {
        int r = row0 + wm * 32 + mt * 16 + gid;
#pragma unroll
        for (int nt = 0; nt < 4; nt++) {
            int col = n0 + wn * 32 + nt * 8 + tig * 2;
            float bx = 0.f, by = 0.f;
            if (!second) { float2 bv = *(const float2*)(b1 + col); bx = bv.x; by = bv.y; }
            g_sh[r * H2 + (col >> 1)]       = pack_h2(acc[mt][nt][0] + bx, acc[mt][nt][1] + by);
            g_sh[(r + 8) * H2 + (col >> 1)] = pack_h2(acc[mt][nt][2] + bx, acc[mt][nt][3] + by);
        }
    }
}

/* ===== score: 128 CTAs x 512 thr (16 warps), 64i x 32j per CTA ===== */
__global__ void __launch_bounds__(512) score_kernel(const float* __restrict__ W2)
{
    __shared__ unsigned s1s[64 * 128];   /* [i][hh] half2, 32 KB           */
    __shared__ unsigned s2s[32 * 129];   /* [j][hh] pad 129: conflict-free */
    __shared__ float2   w2s[128];
    __shared__ float    colbuf[16][32];

    const int jh = blockIdx.x, b = blockIdx.y;
    const int tid = threadIdx.x, lane = tid & 31, w = tid >> 5;

    if (tid < 128) w2s[tid] = *(const float2*)(W2 + tid * 2);

    /* s1: all 64 rows x 128 half2 = 2048 uint4 (4/thread), linear */
    const unsigned* s1g = g_sh + (b * NATOMS) * H2;
#pragma unroll
    for (int l = 0; l < 4; l++) {
        int f = tid + l * 512;
        *(uint4*)&s1s[f * 4] = *(const uint4*)(s1g + f * 4);
    }
    /* s2: 32 rows, pad-129 scalar stores (2 uint4/thread) */
    const unsigned* s2g = g_sh + (BATCH * NATOMS + b * NATOMS + jh * 32) * H2;
#pragma unroll
    for (int l = 0; l < 2; l++) {
        int f = tid + l * 512;
        int j = f >> 5, q = f & 31;
        uint4 v = *(const uint4*)(s2g + f * 4);
        unsigned* d = &s2s[j * 129 + q * 4];
        d[0] = v.x; d[1] = v.y; d[2] = v.z; d[3] = v.w;
    }
    __syncthreads();

    /* warp w owns i rows [w*4, w*4+4), lane = local j — R2-proven loop */
    const unsigned* s2row = &s2s[lane * 129];
    float accA[4], accB[4];
#pragma unroll
    for (int ii = 0; ii < 4; ii++) { accA[ii] = 0.f; accB[ii] = 0.f; }

#pragma unroll 4
    for (int hh = 0; hh < 128; hh++) {
        float2 wv = w2s[hh];           /* broadcast */
        unsigned b2 = s2row[hh];       /* conflict-free */
#pragma unroll
        for (int ii = 0; ii < 4; ii++) {
            unsigned a2 = s1s[(w * 4 + ii) * 128 + hh];   /* broadcast */
            unsigned th = tanh2u(hadd2u(a2, b2));
            float2 tf = __half22float2(u2h(th));
            accA[ii] = fmaf(wv.x, tf.x, accA[ii]);
            accB[ii] = fmaf(wv.y, tf.y, accB[ii]);
        }
    }

    float colacc = 0.f;
#pragma unroll
    for (int ii = 0; ii < 4; ii++) {
        float e = __expf(accA[ii] + accB[ii]);   /* bounded: no max pass */
        colacc += e;
        float rs = e;
#pragma unroll
        for (int o = 16; o > 0; o >>= 1)
            rs += __shfl_xor_sync(0xffffffffu, rs, o);
        if (lane == 0)
            g_rp[(b * NATOMS + w * 4 + ii) * 2 + jh] = rs;
    }
    colbuf[w][lane] = colacc;
    __syncthreads();
    if (tid < 32) {
        float s = 0.f;
#pragma unroll
        for (int ww = 0; ww < 16; ww++) s += colbuf[ww][tid];
        g_c[b * NATOMS + jh * 32 + tid] = s;   /* complete column sum */
    }
}

/* ---------------- normalize ---------------- */
__global__ void __launch_bounds__(64) finalize_kernel(float* __restrict__ out)
{
    int b = blockIdx.x, i = threadIdx.x;
    float r = g_rp[(b * 64 + i) * 2] + g_rp[(b * 64 + i) * 2 + 1];
    float c = g_c[b * 64 + i];
    __shared__ float red[64];
    red[i] = r;
    __syncthreads();
    if (i < 32) {
        float v = red[i] + red[i + 32];
#pragma unroll
        for (int o = 16; o > 0; o >>= 1)
            v += __shfl_xor_sync(0xffffffffu, v, o);
        if (i == 0) red[0] = v;
    }
    __syncthreads();
    float inv = 1.f / red[0];
    out[b * 64 + i] = r * inv;
    out[BATCH * NATOMS + b * 64 + i] = c * inv;
}

extern "C" void kernel_launch(void* const* d_in, const int* in_sizes, int n_in,
                              void* d_out, int out_size)
{
    const float *h1 = nullptr, *h2 = nullptr, *W1 = nullptr,
                *b1 = nullptr, *W2 = nullptr;
    for (int idx = 0; idx < n_in; idx++) {
        int sz = in_sizes[idx];
        if (sz == BATCH * NATOMS * HDIM) {
            if (!h1) h1 = (const float*)d_in[idx];
            else if (!h2) h2 = (const float*)d_in[idx];
        } else if (sz == 2 * HDIM * HDIM) {
            W1 = (const float*)d_in[idx];
        } else if (sz == HDIM) {
            if (!b1) b1 = (const float*)d_in[idx];
            else if (!W2) W2 = (const float*)d_in[idx];
        }
    }
    float* out = (float*)d_out;

    gemm_kernel<<<dim3(NROWS / 64, HDIM / 64), 128>>>(h1, h2, W1, b1);
    score_kernel<<<dim3(2, BATCH), 512>>>(W2);
    finalize_kernel<<<BATCH, 64>>>(out);
}